// round 15
// baseline (speedup 1.0000x reference)
#include <cuda_runtime.h>
#include <cuda_bf16.h>

// RKN scan R15: lane-pair diagonal split (row r = tid>>1, sub = tid&1),
// intra-warp carry combine via shfl_xor(1) -> ONE barrier per step,
// double-buffered state/red. sub0: d0,d1 regs + fp32 diag smem;
// sub1: d2,d4 regs + d5,d6 smem. Deferred-norm softmax, rcp.approx.

#define NB   128
#define NT   128
#define NLOD 128
#define NK   16

// dynamic smem layout (bytes)
static constexpr int DG_OFF  = 0;                        // float4[NK*NLOD] diag fp32
static constexpr int OD_OFF  = DG_OFF + NK * NLOD * 16;  // uint4[NK*NLOD] d5,d6
static constexpr int ST_OFF  = OD_OFF + NK * NLOD * 16;  // float4[2][136] state
static constexpr int CS_OFF  = ST_OFF + 2 * 136 * 16;    // float[2][136]
static constexpr int RED_OFF = CS_OFF + 2 * 136 * 4;     // float[2][128]
static constexpr int SMEM_BYTES = RED_OFF + 2 * 128 * 4; // ~71.5 KB

__device__ __forceinline__ unsigned int pk(float a, float b) {
    __nv_bfloat162 t = __floats2bfloat162_rn(a, b);
    return reinterpret_cast<unsigned int&>(t);
}
// acc(f32x2) += { lo: p<<16 (exact), hi: raw p (garbage low mantissa) } * {a,a}
__device__ __forceinline__ void pair_fma(unsigned long long& acc,
                                         unsigned int p, unsigned long long a2) {
    asm("{\n\t.reg .b32 lo;\n\t.reg .b64 v;\n\t"
        "shl.b32 lo, %1, 16;\n\t"
        "mov.b64 v, {lo, %1};\n\t"
        "fma.rn.f32x2 %0, v, %2, %0;\n\t}"
        : "+l"(acc) : "r"(p), "l"(a2));
}
__device__ __forceinline__ unsigned long long dup2(float a) {
    unsigned long long r;
    asm("mov.b64 %0, {%1, %1};" : "=l"(r) : "f"(a));
    return r;
}
__device__ __forceinline__ void unpk2(unsigned long long r, float& x, float& y) {
    asm("mov.b64 {%0, %1}, %2;" : "=f"(x), "=f"(y) : "l"(r));
}
__device__ __forceinline__ float frcp(float x) {
    float r;
    asm("rcp.approx.f32 %0, %1;" : "=f"(r) : "f"(x));
    return r;
}

// value-split round: v[0..2m-1] -> v[0..m-1], lane bit M picks upper half
#define VS_ROUND(M, m)                                                        \
  _Pragma("unroll")                                                           \
  for (int kk = 0; kk < (m); kk++) {                                          \
    float a_ = v[kk], c_ = v[kk + (m)];                                       \
    bool  hi_ = (lane & (M)) != 0;                                            \
    float keep_ = hi_ ? c_ : a_;                                              \
    float send_ = hi_ ? a_ : c_;                                              \
    v[kk] = keep_ + __shfl_xor_sync(0xffffffffu, send_, (M));                 \
  }

// normalize by inv, then accumulate one diagonal's matvec contribution
#define BAND_NORM_ACC(d, A11, A12, A21, A22)                                  \
  {                                                                           \
    float a11 = (A11) * inv, a12 = (A12) * inv;                               \
    float a21 = (A21) * inv, a22 = (A22) * inv;                               \
    float4 st_ = stb[r + (d)];                                                \
    float  csj = csb[r + (d)];                                                \
    float muj = st_.x, mlj = st_.y, cuj = st_.z, clj = st_.w;                 \
    nmu = fmaf(a11, muj, nmu); nmu = fmaf(a12, mlj, nmu);                     \
    nml = fmaf(a21, muj, nml); nml = fmaf(a22, mlj, nml);                     \
    ncu = fmaf(a11 * a11, cuj, ncu);                                          \
    ncu = fmaf(2.0f * a11 * a12, csj, ncu);                                   \
    ncu = fmaf(a12 * a12, clj, ncu);                                          \
    ncl = fmaf(a21 * a21, cuj, ncl);                                          \
    ncl = fmaf(2.0f * a21 * a22, csj, ncl);                                   \
    ncl = fmaf(a22 * a22, clj, ncl);                                          \
    ncs = fmaf(a21 * a11, cuj, ncs);                                          \
    ncs = fmaf(fmaf(a22, a11, a21 * a12), csj, ncs);                          \
    ncs = fmaf(a22 * a12, clj, ncs);                                          \
  }

__global__ void __launch_bounds__(256, 1)
rkn_kernel(const float* __restrict__ lobs,   // (B,T,LOD)
           const float* __restrict__ ovars,  // (B,T,LOD)
           const float* __restrict__ imean,  // (B,2*LOD)
           const float* __restrict__ icu,
           const float* __restrict__ icl,
           const float* __restrict__ ics,
           const float* __restrict__ tm11,   // (K,LOD,LOD)
           const float* __restrict__ tm12,
           const float* __restrict__ tm21,
           const float* __restrict__ tm22,
           const float* __restrict__ cw,     // (2*LOD, K)
           const float* __restrict__ cb,     // (K,)
           const float* __restrict__ tcu,
           const float* __restrict__ tcl,
           float* __restrict__ out)
{
    extern __shared__ char smraw[];
    float4* dg   = reinterpret_cast<float4*>(smraw + DG_OFF);
    uint4*  od   = reinterpret_cast<uint4*>(smraw + OD_OFF);
    float4* s_st = reinterpret_cast<float4*>(smraw + ST_OFF);   // [2][136]
    float*  s_cs = reinterpret_cast<float*>(smraw + CS_OFF);    // [2][136]
    float*  red  = reinterpret_cast<float*>(smraw + RED_OFF);   // [2][128]

    const int b    = blockIdx.x;
    const int tid  = threadIdx.x;
    const int lane = tid & 31;
    const int w    = tid >> 5;      // warp 0..7
    const int r    = tid >> 1;      // row 0..127 (pair-shared)
    const int sub  = tid & 1;       // diagonal sub-slot
    const int k0h  = sub << 3;      // this slot's logit k-range base

    // ---- prologue: smem tables ----
    for (int rr = tid; rr < NK * NLOD; rr += 256) {
        int k = rr >> 7, ii = rr & 127;
        long base = ((long)k * NLOD + ii) * NLOD;
        dg[rr] = make_float4(__ldg(tm11 + base + ii), __ldg(tm12 + base + ii),
                             __ldg(tm21 + base + ii), __ldg(tm22 + base + ii));
        int j5 = ii + 2, j6 = ii + 3;
        float e11 = 0.f, e12 = 0.f, e21 = 0.f, e22 = 0.f;
        float f11 = 0.f, f12 = 0.f, f21 = 0.f, f22 = 0.f;
        if (j5 < NLOD) {
            e11 = __ldg(tm11 + base + j5); e12 = __ldg(tm12 + base + j5);
            e21 = __ldg(tm21 + base + j5); e22 = __ldg(tm22 + base + j5);
        }
        if (j6 < NLOD) {
            f11 = __ldg(tm11 + base + j6); f12 = __ldg(tm12 + base + j6);
            f21 = __ldg(tm21 + base + j6); f22 = __ldg(tm22 + base + j6);
        }
        od[rr] = make_uint4(pk(e11, e12), pk(e21, e22),
                            pk(f11, f12), pk(f21, f22));
    }
    // zero both state buffers (covers guard cells)
    for (int idx = tid; idx < 2 * 136; idx += 256) {
        s_st[idx] = make_float4(0.f, 0.f, 0.f, 0.f);
        s_cs[idx] = 0.f;
    }

    const float bbl  = __ldg(cb + (lane & 15));
    const float tcur = __ldg(tcu + r);
    const float tclr = __ldg(tcl + r);

    // this slot's 8 softmax-weight columns for row r
    float Wu[8], Wl[8];
    #pragma unroll
    for (int kk = 0; kk < 8; kk++) {
        Wu[kk] = __ldg(cw + r * NK + k0h + kk);
        Wl[kk] = __ldg(cw + (NLOD + r) * NK + k0h + kk);
    }

    // full carry in registers (both lanes of the pair hold identical values)
    float cmu = imean[(long)b * 2 * NLOD + r];
    float cml = imean[(long)b * 2 * NLOD + NLOD + r];
    float ccu = icu[(long)b * NLOD + r];
    float ccl = icl[(long)b * NLOD + r];
    float ccs = ics[(long)b * NLOD + r];

    const float* obs_p = lobs  + ((long)b * NT) * NLOD + r;
    const float* ov_p  = ovars + ((long)b * NT) * NLOD + r;
    float obs_r = __ldg(obs_p);
    float ov_r  = __ldg(ov_p);
    obs_p += NLOD; ov_p += NLOD;

    // ---- register tables: 2 diagonals per slot ----
    // sub0: d0 (j=r-3), d1 (j=r-2)   |   sub1: d2 (j=r-1), d4 (j=r+1)
    uint4 Ra[NK];
    {
        const int ja = (sub == 0) ? r - 3 : r - 1;
        const int jb = (sub == 0) ? r - 2 : r + 1;
        const bool va = (unsigned)ja < (unsigned)NLOD;
        const bool vb = (unsigned)jb < (unsigned)NLOD;
        #pragma unroll
        for (int k = 0; k < NK; k++) {
            long base = ((long)k * NLOD + r) * NLOD;
            float a11 = 0.f, a12 = 0.f, a21 = 0.f, a22 = 0.f;
            float c11 = 0.f, c12 = 0.f, c21 = 0.f, c22 = 0.f;
            if (va) {
                a11 = __ldg(tm11 + base + ja); a12 = __ldg(tm12 + base + ja);
                a21 = __ldg(tm21 + base + ja); a22 = __ldg(tm22 + base + ja);
            }
            if (vb) {
                c11 = __ldg(tm11 + base + jb); c12 = __ldg(tm12 + base + jb);
                c21 = __ldg(tm21 + base + jb); c22 = __ldg(tm22 + base + jb);
            }
            Ra[k] = make_uint4(pk(a11, a12), pk(a21, a22),
                               pk(c11, c12), pk(c21, c22));
        }
    }

    float* out_pm = out;
    float* out_cu = out + (long)NB * NT * 2 * NLOD;
    float* out_cl = out_cu + (long)NB * NT * NLOD;
    float* out_cs = out_cl + (long)NB * NT * NLOD;

    __syncthreads();

    for (int t = 0; t < NT; t++) {
        const int buf = t & 1;
        float4* stb = s_st + buf * 136;
        float*  csb = s_cs + buf * 136;
        float*  rdb = red  + buf * 128;

        // ========= phase 1: obs update (redundant in pair) + logits =========
        float rd    = frcp(ccu + ov_r);
        float qu    = ccu * rd;
        float ql    = ccs * rd;
        float res   = obs_r - cmu;
        float pu    = cmu + qu * res;
        float pl    = cml + ql * res;
        float cf    = 1.0f - qu;
        float pcu   = cf * ccu;
        float pcl   = ccl - ql * ccs;
        float pcs   = cf * ccs;

        if (t + 1 < NT) {
            obs_r = __ldg(obs_p);
            ov_r  = __ldg(ov_p);
            obs_p += NLOD; ov_p += NLOD;
        }

        long obase = (long)b * NT + t;
        if (sub == 0) {
            stb[3 + r] = make_float4(pu, pl, pcu, pcl);
            csb[3 + r] = pcs;
            out_pm[obase * 2 * NLOD + r]        = pu;
            out_pm[obase * 2 * NLOD + NLOD + r] = pl;
        } else {
            out_cu[obase * NLOD + r] = pcu;
            out_cl[obase * NLOD + r] = pcl;
            out_cs[obase * NLOD + r] = pcs;
        }

        // logits for this slot's 8 k's, reduced over the warp's 16 rows:
        // value-split on lane bits 4,3,2 then fold bit 1 (parity bit 0 kept).
        float v[8];
        #pragma unroll
        for (int kk = 0; kk < 8; kk++) v[kk] = fmaf(pu, Wu[kk], pl * Wl[kk]);
        VS_ROUND(16, 4)    // lane bit4 -> k-bit2
        VS_ROUND(8, 2)     // lane bit3 -> k-bit1
        VS_ROUND(4, 1)     // lane bit2 -> k-bit0
        v[0] += __shfl_xor_sync(0xffffffffu, v[0], 2);
        {
            int klocal = (((lane >> 4) & 1) << 2) | (((lane >> 3) & 1) << 1)
                       | ((lane >> 2) & 1);
            int kfull  = k0h | klocal;
            if ((lane & 2) == 0) rdb[w * 16 + kfull] = v[0];
        }
        __syncthreads();   // the ONLY barrier per step

        // ========= phase 2: softmax (deferred norm) + A-gen + matvec =========
        float w_, s_;
        {
            const int kq = lane & 15;
            float l0 = rdb[0 * 16 + kq] + rdb[1 * 16 + kq];
            float l1 = rdb[2 * 16 + kq] + rdb[3 * 16 + kq];
            float l2 = rdb[4 * 16 + kq] + rdb[5 * 16 + kq];
            float l3 = rdb[6 * 16 + kq] + rdb[7 * 16 + kq];
            float lg = bbl + ((l0 + l1) + (l2 + l3));
            w_ = __expf(lg);       // unnormalized weight for k = lane&15
            s_ = w_;
            #pragma unroll
            for (int m = 8; m >= 1; m >>= 1)
                s_ += __shfl_xor_sync(0xffffffffu, s_, m);
        }

        float nmu = 0.f, nml = 0.f, ncu = 0.f, ncl = 0.f, ncs = 0.f;

        if (sub == 0) {
            // regs: d0,d1 bf16; smem: fp32 diag
            float D11 = 0.f, D12 = 0.f, D21 = 0.f, D22 = 0.f;
            unsigned long long P0 = 0ull, Q0 = 0ull, P1 = 0ull, Q1 = 0ull;
            #pragma unroll
            for (int k = 0; k < NK; k++) {
                float a = __shfl_sync(0xffffffffu, w_, k);
                unsigned long long a2 = dup2(a);
                uint4 rt = Ra[k];
                float4 gv = dg[k * NLOD + r];
                pair_fma(P0, rt.x, a2);
                pair_fma(Q0, rt.y, a2);
                pair_fma(P1, rt.z, a2);
                pair_fma(Q1, rt.w, a2);
                D11 = fmaf(a, gv.x, D11);
                D12 = fmaf(a, gv.y, D12);
                D21 = fmaf(a, gv.z, D21);
                D22 = fmaf(a, gv.w, D22);
            }
            const float inv = frcp(s_);
            float x, y, z, w2;
            unpk2(P0, x, y); unpk2(Q0, z, w2);
            BAND_NORM_ACC(0, x, y, z, w2)
            unpk2(P1, x, y); unpk2(Q1, z, w2);
            BAND_NORM_ACC(1, x, y, z, w2)
            {   // diagonal: A = D*inv + I
                float a11 = fmaf(D11, inv, 1.0f), a12 = D12 * inv;
                float a21 = D21 * inv, a22 = fmaf(D22, inv, 1.0f);
                float4 st_ = stb[r + 3];
                float  csj = csb[r + 3];
                float muj = st_.x, mlj = st_.y, cuj = st_.z, clj = st_.w;
                nmu = fmaf(a11, muj, nmu); nmu = fmaf(a12, mlj, nmu);
                nml = fmaf(a21, muj, nml); nml = fmaf(a22, mlj, nml);
                ncu = fmaf(a11 * a11, cuj, ncu);
                ncu = fmaf(2.0f * a11 * a12, csj, ncu);
                ncu = fmaf(a12 * a12, clj, ncu);
                ncl = fmaf(a21 * a21, cuj, ncl);
                ncl = fmaf(2.0f * a21 * a22, csj, ncl);
                ncl = fmaf(a22 * a22, clj, ncl);
                ncs = fmaf(a21 * a11, cuj, ncs);
                ncs = fmaf(fmaf(a22, a11, a21 * a12), csj, ncs);
                ncs = fmaf(a22 * a12, clj, ncs);
            }
        } else {
            // regs: d2,d4 bf16; smem: d5,d6 bf16
            unsigned long long P2 = 0ull, Q2 = 0ull, P4 = 0ull, Q4 = 0ull;
            unsigned long long P5 = 0ull, Q5 = 0ull, P6 = 0ull, Q6 = 0ull;
            #pragma unroll
            for (int k = 0; k < NK; k++) {
                unsigned long long a2 = dup2(__shfl_sync(0xffffffffu, w_, k));
                uint4 rt = Ra[k];
                uint4 ro = od[k * NLOD + r];
                pair_fma(P2, rt.x, a2);
                pair_fma(Q2, rt.y, a2);
                pair_fma(P4, rt.z, a2);
                pair_fma(Q4, rt.w, a2);
                pair_fma(P5, ro.x, a2);
                pair_fma(Q5, ro.y, a2);
                pair_fma(P6, ro.z, a2);
                pair_fma(Q6, ro.w, a2);
            }
            const float inv = frcp(s_);
            float x, y, z, w2;
            unpk2(P2, x, y); unpk2(Q2, z, w2);
            BAND_NORM_ACC(2, x, y, z, w2)
            unpk2(P4, x, y); unpk2(Q4, z, w2);
            BAND_NORM_ACC(4, x, y, z, w2)
            unpk2(P5, x, y); unpk2(Q5, z, w2);
            BAND_NORM_ACC(5, x, y, z, w2)
            unpk2(P6, x, y); unpk2(Q6, z, w2);
            BAND_NORM_ACC(6, x, y, z, w2)
        }

        // ---- intra-warp pair combine: both lanes end with the full carry ----
        cmu = nmu + __shfl_xor_sync(0xffffffffu, nmu, 1);
        cml = nml + __shfl_xor_sync(0xffffffffu, nml, 1);
        ccu = (ncu + __shfl_xor_sync(0xffffffffu, ncu, 1)) + tcur;
        ccl = (ncl + __shfl_xor_sync(0xffffffffu, ncl, 1)) + tclr;
        ccs = ncs + __shfl_xor_sync(0xffffffffu, ncs, 1);
        // no second barrier: next phase-1 writes the OTHER buffer
    }
}

extern "C" void kernel_launch(void* const* d_in, const int* in_sizes, int n_in,
                              void* d_out, int out_size)
{
    (void)in_sizes; (void)n_in; (void)out_size;
    const float* lobs  = (const float*)d_in[0];
    const float* ovars = (const float*)d_in[1];
    const float* imean = (const float*)d_in[2];
    const float* icu   = (const float*)d_in[3];
    const float* icl   = (const float*)d_in[4];
    const float* ics   = (const float*)d_in[5];
    const float* tm11  = (const float*)d_in[6];
    const float* tm12  = (const float*)d_in[7];
    const float* tm21  = (const float*)d_in[8];
    const float* tm22  = (const float*)d_in[9];
    const float* cw    = (const float*)d_in[10];
    const float* cb    = (const float*)d_in[11];
    const float* tcu   = (const float*)d_in[12];
    const float* tcl   = (const float*)d_in[13];
    float* out = (float*)d_out;

    cudaFuncSetAttribute(rkn_kernel,
                         cudaFuncAttributeMaxDynamicSharedMemorySize, SMEM_BYTES);

    rkn_kernel<<<NB, 256, SMEM_BYTES>>>(lobs, ovars, imean, icu, icl, ics,
                                        tm11, tm12, tm21, tm22,
                                        cw, cb, tcu, tcl, out);
}

// round 16
// speedup vs baseline: 2.4545x; 2.4545x over previous
#include <cuda_runtime.h>
#include <cuda_bf16.h>

// RKN scan R16: lane-pair split with FULLY CONVERGENT phase 2.
// row r = tid>>1, sub = tid&1. Each sub: 2 reg diagonals + 2 smem slots,
// identical instruction streams (d3 stored as bf16 hi+lo planes for sub0).
// Intra-warp pair combine (shfl_xor 1) -> ONE barrier/step, double-buffered.

#define NB   128
#define NT   128
#define NLOD 128
#define NK   16

// dynamic smem layout (bytes)
static constexpr int DG_OFF  = 0;                        // uint4[NK*NLOD] d3 hi/lo bf16
static constexpr int OD_OFF  = DG_OFF + NK * NLOD * 16;  // uint4[NK*NLOD] d5,d6 bf16
static constexpr int ST_OFF  = OD_OFF + NK * NLOD * 16;  // float4[2][136] state
static constexpr int CS_OFF  = ST_OFF + 2 * 136 * 16;    // float[2][136]
static constexpr int RED_OFF = CS_OFF + 2 * 136 * 4;     // float[2][128]
static constexpr int SMEM_BYTES = RED_OFF + 2 * 128 * 4; // ~71.5 KB

__device__ __forceinline__ unsigned int pk(float a, float b) {
    __nv_bfloat162 t = __floats2bfloat162_rn(a, b);
    return reinterpret_cast<unsigned int&>(t);
}
// cheap: acc += { lo: p<<16 exact, hi: raw p (2^-8 garbage) } * {a,a}
__device__ __forceinline__ void pair_fma(unsigned long long& acc,
                                         unsigned int p, unsigned long long a2) {
    asm("{\n\t.reg .b32 lo;\n\t.reg .b64 v;\n\t"
        "shl.b32 lo, %1, 16;\n\t"
        "mov.b64 v, {lo, %1};\n\t"
        "fma.rn.f32x2 %0, v, %2, %0;\n\t}"
        : "+l"(acc) : "r"(p), "l"(a2));
}
// exact: acc += { p<<16, p&0xFFFF0000 } * {a,a}  (both elements exact bf16)
__device__ __forceinline__ void pair_fma_x(unsigned long long& acc,
                                           unsigned int p, unsigned long long a2) {
    asm("{\n\t.reg .b32 lo, hx;\n\t.reg .b64 v;\n\t"
        "shl.b32 lo, %1, 16;\n\t"
        "and.b32 hx, %1, 0xFFFF0000;\n\t"
        "mov.b64 v, {lo, hx};\n\t"
        "fma.rn.f32x2 %0, v, %2, %0;\n\t}"
        : "+l"(acc) : "r"(p), "l"(a2));
}
__device__ __forceinline__ unsigned long long dup2(float a) {
    unsigned long long r;
    asm("mov.b64 %0, {%1, %1};" : "=l"(r) : "f"(a));
    return r;
}
__device__ __forceinline__ void unpk2(unsigned long long r, float& x, float& y) {
    asm("mov.b64 {%0, %1}, %2;" : "=f"(x), "=f"(y) : "l"(r));
}
__device__ __forceinline__ float frcp(float x) {
    float r;
    asm("rcp.approx.f32 %0, %1;" : "=f"(r) : "f"(x));
    return r;
}

// value-split round: v[0..2m-1] -> v[0..m-1], lane bit M picks upper half
#define VS_ROUND(M, m)                                                        \
  _Pragma("unroll")                                                           \
  for (int kk = 0; kk < (m); kk++) {                                          \
    float a_ = v[kk], c_ = v[kk + (m)];                                       \
    bool  hi_ = (lane & (M)) != 0;                                            \
    float keep_ = hi_ ? c_ : a_;                                              \
    float send_ = hi_ ? a_ : c_;                                              \
    v[kk] = keep_ + __shfl_xor_sync(0xffffffffu, send_, (M));                 \
  }

// accumulate one diagonal's matvec contribution (a's pre-normalized)
#define BAND_ACC(d, a11, a12, a21, a22)                                       \
  {                                                                           \
    float4 st_ = stb[r + (d)];                                                \
    float  csj = csb[r + (d)];                                                \
    float muj = st_.x, mlj = st_.y, cuj = st_.z, clj = st_.w;                 \
    nmu = fmaf((a11), muj, nmu); nmu = fmaf((a12), mlj, nmu);                 \
    nml = fmaf((a21), muj, nml); nml = fmaf((a22), mlj, nml);                 \
    ncu = fmaf((a11) * (a11), cuj, ncu);                                      \
    ncu = fmaf(2.0f * (a11) * (a12), csj, ncu);                               \
    ncu = fmaf((a12) * (a12), clj, ncu);                                      \
    ncl = fmaf((a21) * (a21), cuj, ncl);                                      \
    ncl = fmaf(2.0f * (a21) * (a22), csj, ncl);                               \
    ncl = fmaf((a22) * (a22), clj, ncl);                                      \
    ncs = fmaf((a21) * (a11), cuj, ncs);                                      \
    ncs = fmaf(fmaf((a22), (a11), (a21) * (a12)), csj, ncs);                  \
    ncs = fmaf((a22) * (a12), clj, ncs);                                      \
  }

__global__ void __launch_bounds__(256, 1)
rkn_kernel(const float* __restrict__ lobs,   // (B,T,LOD)
           const float* __restrict__ ovars,  // (B,T,LOD)
           const float* __restrict__ imean,  // (B,2*LOD)
           const float* __restrict__ icu,
           const float* __restrict__ icl,
           const float* __restrict__ ics,
           const float* __restrict__ tm11,   // (K,LOD,LOD)
           const float* __restrict__ tm12,
           const float* __restrict__ tm21,
           const float* __restrict__ tm22,
           const float* __restrict__ cw,     // (2*LOD, K)
           const float* __restrict__ cb,     // (K,)
           const float* __restrict__ tcu,
           const float* __restrict__ tcl,
           float* __restrict__ out)
{
    extern __shared__ char smraw[];
    uint4*  dgx  = reinterpret_cast<uint4*>(smraw + DG_OFF);    // d3 hi/lo
    uint4*  od   = reinterpret_cast<uint4*>(smraw + OD_OFF);    // d5,d6
    float4* s_st = reinterpret_cast<float4*>(smraw + ST_OFF);   // [2][136]
    float*  s_cs = reinterpret_cast<float*>(smraw + CS_OFF);    // [2][136]
    float*  red  = reinterpret_cast<float*>(smraw + RED_OFF);   // [2][128]

    const int b    = blockIdx.x;
    const int tid  = threadIdx.x;
    const int lane = tid & 31;
    const int w    = tid >> 5;      // warp 0..7
    const int r    = tid >> 1;      // row 0..127 (pair-shared)
    const int sub  = tid & 1;       // slot half

    // ---- prologue: smem tables ----
    for (int rr = tid; rr < NK * NLOD; rr += 256) {
        int k = rr >> 7, ii = rr & 127;
        long base = ((long)k * NLOD + ii) * NLOD;
        // d3 diagonal, split hi/lo bf16
        float v11 = __ldg(tm11 + base + ii), v12 = __ldg(tm12 + base + ii);
        float v21 = __ldg(tm21 + base + ii), v22 = __ldg(tm22 + base + ii);
        float h11 = __bfloat162float(__float2bfloat16(v11));
        float h12 = __bfloat162float(__float2bfloat16(v12));
        float h21 = __bfloat162float(__float2bfloat16(v21));
        float h22 = __bfloat162float(__float2bfloat16(v22));
        dgx[rr] = make_uint4(pk(h11, h12), pk(h21, h22),
                             pk(v11 - h11, v12 - h12), pk(v21 - h21, v22 - h22));
        int j5 = ii + 2, j6 = ii + 3;
        float e11 = 0.f, e12 = 0.f, e21 = 0.f, e22 = 0.f;
        float f11 = 0.f, f12 = 0.f, f21 = 0.f, f22 = 0.f;
        if (j5 < NLOD) {
            e11 = __ldg(tm11 + base + j5); e12 = __ldg(tm12 + base + j5);
            e21 = __ldg(tm21 + base + j5); e22 = __ldg(tm22 + base + j5);
        }
        if (j6 < NLOD) {
            f11 = __ldg(tm11 + base + j6); f12 = __ldg(tm12 + base + j6);
            f21 = __ldg(tm21 + base + j6); f22 = __ldg(tm22 + base + j6);
        }
        od[rr] = make_uint4(pk(e11, e12), pk(e21, e22),
                            pk(f11, f12), pk(f21, f22));
    }
    for (int idx = tid; idx < 2 * 136; idx += 256) {
        s_st[idx] = make_float4(0.f, 0.f, 0.f, 0.f);
        s_cs[idx] = 0.f;
    }

    const float bbl  = __ldg(cb + (lane & 15));
    const float tcur = __ldg(tcu + r);
    const float tclr = __ldg(tcl + r);

    const int k0h = sub << 3;       // this slot's logit k-range base
    float Wu[8], Wl[8];
    #pragma unroll
    for (int kk = 0; kk < 8; kk++) {
        Wu[kk] = __ldg(cw + r * NK + k0h + kk);
        Wl[kk] = __ldg(cw + (NLOD + r) * NK + k0h + kk);
    }

    // full carry in registers (both lanes of a pair hold identical values)
    float cmu = imean[(long)b * 2 * NLOD + r];
    float cml = imean[(long)b * 2 * NLOD + NLOD + r];
    float ccu = icu[(long)b * NLOD + r];
    float ccl = icl[(long)b * NLOD + r];
    float ccs = ics[(long)b * NLOD + r];

    const float* obs_p = lobs  + ((long)b * NT) * NLOD + r;
    const float* ov_p  = ovars + ((long)b * NT) * NLOD + r;
    float obs_r = __ldg(obs_p);
    float ov_r  = __ldg(ov_p);
    obs_p += NLOD; ov_p += NLOD;

    // ---- register tables: 2 diagonals per slot ----
    // sub0: d0 (j=r-3), d1 (j=r-2)   |   sub1: d2 (j=r-1), d4 (j=r+1)
    uint4 Ra[NK];
    {
        const int ja = (sub == 0) ? r - 3 : r - 1;
        const int jb = (sub == 0) ? r - 2 : r + 1;
        const bool va = (unsigned)ja < (unsigned)NLOD;
        const bool vb = (unsigned)jb < (unsigned)NLOD;
        #pragma unroll
        for (int k = 0; k < NK; k++) {
            long base = ((long)k * NLOD + r) * NLOD;
            float a11 = 0.f, a12 = 0.f, a21 = 0.f, a22 = 0.f;
            float c11 = 0.f, c12 = 0.f, c21 = 0.f, c22 = 0.f;
            if (va) {
                a11 = __ldg(tm11 + base + ja); a12 = __ldg(tm12 + base + ja);
                a21 = __ldg(tm21 + base + ja); a22 = __ldg(tm22 + base + ja);
            }
            if (vb) {
                c11 = __ldg(tm11 + base + jb); c12 = __ldg(tm12 + base + jb);
                c21 = __ldg(tm21 + base + jb); c22 = __ldg(tm22 + base + jb);
            }
            Ra[k] = make_uint4(pk(a11, a12), pk(a21, a22),
                               pk(c11, c12), pk(c21, c22));
        }
    }

    // per-lane table/constants for the convergent phase-2 tail
    const uint4* sm_tab = (sub == 0) ? dgx : od;   // smem stream
    const int dA = sub ? 2 : 0;
    const int dB = sub ? 4 : 1;
    const int dC = sub ? 5 : 3;
    const int dD = sub ? 6 : 3;       // sub0 slot3 is a zero dummy
    const float mrg = sub ? 0.f : 1.f;   // fold slot3 into slot2 (+I) for sub0
    const float km  = 1.f - mrg;

    float* out_pm = out;
    float* out_cu = out + (long)NB * NT * 2 * NLOD;
    float* out_cl = out_cu + (long)NB * NT * NLOD;
    float* out_cs = out_cl + (long)NB * NT * NLOD;

    __syncthreads();

    for (int t = 0; t < NT; t++) {
        const int buf = t & 1;
        float4* stb = s_st + buf * 136;
        float*  csb = s_cs + buf * 136;
        float*  rdb = red  + buf * 128;

        // ========= phase 1: obs update (redundant in pair) + logits =========
        float rd    = frcp(ccu + ov_r);
        float qu    = ccu * rd;
        float ql    = ccs * rd;
        float res   = obs_r - cmu;
        float pu    = cmu + qu * res;
        float pl    = cml + ql * res;
        float cf    = 1.0f - qu;
        float pcu   = cf * ccu;
        float pcl   = ccl - ql * ccs;
        float pcs   = cf * ccs;

        if (t + 1 < NT) {
            obs_r = __ldg(obs_p);
            ov_r  = __ldg(ov_p);
            obs_p += NLOD; ov_p += NLOD;
        }

        long obase = (long)b * NT + t;
        if (sub == 0) {
            stb[3 + r] = make_float4(pu, pl, pcu, pcl);
            csb[3 + r] = pcs;
            out_pm[obase * 2 * NLOD + r]        = pu;
            out_pm[obase * 2 * NLOD + NLOD + r] = pl;
        } else {
            out_cu[obase * NLOD + r] = pcu;
            out_cl[obase * NLOD + r] = pcl;
            out_cs[obase * NLOD + r] = pcs;
        }

        // logits: 8 k's per slot over the warp's 16 rows.
        // VS on lane bits 4,3,2 (k bits 2,1,0), fold row bit (lane bit 1).
        float v[8];
        #pragma unroll
        for (int kk = 0; kk < 8; kk++) v[kk] = fmaf(pu, Wu[kk], pl * Wl[kk]);
        VS_ROUND(16, 4)
        VS_ROUND(8, 2)
        VS_ROUND(4, 1)
        v[0] += __shfl_xor_sync(0xffffffffu, v[0], 2);
        {
            int klocal = (((lane >> 4) & 1) << 2) | (((lane >> 3) & 1) << 1)
                       | ((lane >> 2) & 1);
            int kfull  = k0h | klocal;
            if ((lane & 2) == 0) rdb[w * 16 + kfull] = v[0];
        }
        __syncthreads();   // the ONLY barrier per step

        // ========= phase 2 (CONVERGENT): softmax + A-gen + matvec =========
        float w_, s_;
        {
            const int kq = lane & 15;
            float l0 = rdb[0 * 16 + kq] + rdb[1 * 16 + kq];
            float l1 = rdb[2 * 16 + kq] + rdb[3 * 16 + kq];
            float l2 = rdb[4 * 16 + kq] + rdb[5 * 16 + kq];
            float l3 = rdb[6 * 16 + kq] + rdb[7 * 16 + kq];
            float lg = bbl + ((l0 + l1) + (l2 + l3));
            w_ = __expf(lg);       // unnormalized weight for k = lane&15
            s_ = w_;
            #pragma unroll
            for (int m = 8; m >= 1; m >>= 1)
                s_ += __shfl_xor_sync(0xffffffffu, s_, m);
        }

        unsigned long long PA = 0ull, QA = 0ull, PB = 0ull, QB = 0ull;
        unsigned long long PC = 0ull, QC = 0ull, PD = 0ull, QD = 0ull;
        #pragma unroll
        for (int k = 0; k < NK; k++) {
            unsigned long long a2 = dup2(__shfl_sync(0xffffffffu, w_, k));
            uint4 rt = Ra[k];
            uint4 ro = sm_tab[k * NLOD + r];
            pair_fma(PA, rt.x, a2);
            pair_fma(QA, rt.y, a2);
            pair_fma(PB, rt.z, a2);
            pair_fma(QB, rt.w, a2);
            pair_fma_x(PC, ro.x, a2);
            pair_fma_x(QC, ro.y, a2);
            pair_fma_x(PD, ro.z, a2);
            pair_fma_x(QD, ro.w, a2);
        }

        const float inv = frcp(s_);
        float nmu = 0.f, nml = 0.f, ncu = 0.f, ncl = 0.f, ncs = 0.f;
        float x, y, z, ww, x2, y2, z2, w2;
        // slot 0
        unpk2(PA, x, y); unpk2(QA, z, ww);
        BAND_ACC(dA, x * inv, y * inv, z * inv, ww * inv)
        // slot 1
        unpk2(PB, x, y); unpk2(QB, z, ww);
        BAND_ACC(dB, x * inv, y * inv, z * inv, ww * inv)
        // slot 2 (+ mrg*slot3 + mrg*I) and slot 3 ((1-mrg)*slot3)
        unpk2(PC, x, y); unpk2(QC, z, ww);
        unpk2(PD, x2, y2); unpk2(QD, z2, w2);
        {
            float c11 = fmaf(mrg, x2, x), c12 = fmaf(mrg, y2, y);
            float c21 = fmaf(mrg, z2, z), c22 = fmaf(mrg, w2, ww);
            BAND_ACC(dC, fmaf(c11, inv, mrg), c12 * inv,
                         c21 * inv, fmaf(c22, inv, mrg))
        }
        {
            float kinv = km * inv;
            BAND_ACC(dD, x2 * kinv, y2 * kinv, z2 * kinv, w2 * kinv)
        }

        // ---- intra-warp pair combine (convergent) ----
        cmu = nmu + __shfl_xor_sync(0xffffffffu, nmu, 1);
        cml = nml + __shfl_xor_sync(0xffffffffu, nml, 1);
        ccu = (ncu + __shfl_xor_sync(0xffffffffu, ncu, 1)) + tcur;
        ccl = (ncl + __shfl_xor_sync(0xffffffffu, ncl, 1)) + tclr;
        ccs = ncs + __shfl_xor_sync(0xffffffffu, ncs, 1);
        // no second barrier: next phase-1 writes the OTHER buffer
    }
}

extern "C" void kernel_launch(void* const* d_in, const int* in_sizes, int n_in,
                              void* d_out, int out_size)
{
    (void)in_sizes; (void)n_in; (void)out_size;
    const float* lobs  = (const float*)d_in[0];
    const float* ovars = (const float*)d_in[1];
    const float* imean = (const float*)d_in[2];
    const float* icu   = (const float*)d_in[3];
    const float* icl   = (const float*)d_in[4];
    const float* ics   = (const float*)d_in[5];
    const float* tm11  = (const float*)d_in[6];
    const float* tm12  = (const float*)d_in[7];
    const float* tm21  = (const float*)d_in[8];
    const float* tm22  = (const float*)d_in[9];
    const float* cw    = (const float*)d_in[10];
    const float* cb    = (const float*)d_in[11];
    const float* tcu   = (const float*)d_in[12];
    const float* tcl   = (const float*)d_in[13];
    float* out = (float*)d_out;

    cudaFuncSetAttribute(rkn_kernel,
                         cudaFuncAttributeMaxDynamicSharedMemorySize, SMEM_BYTES);

    rkn_kernel<<<NB, 256, SMEM_BYTES>>>(lobs, ovars, imean, icu, icl, ics,
                                        tm11, tm12, tm21, tm22,
                                        cw, cb, tcu, tcl, out);
}